// round 15
// baseline (speedup 1.0000x reference)
#include <cuda_runtime.h>
#include <math.h>

#define DDIM 2048
#define DEPTH 9
#define BM 128
#define BN 128
#define BK 32
#define TMP 4                             // row PAIRS per thread (8 rows)
#define TN 4                              // cols per thread
#define NTHREADS 512
#define NCHUNK 4
#define TILES_PER_CHUNK ((DDIM / NCHUNK) / BK)   // 16
#define NTILES (DDIM / BK)                        // 64

#define AS_ROW (BM + 4)                 // 132 floats
#define BS_ROW (BN + 4)                 // 132 floats
#define AS_BYTES (BK * AS_ROW * 4)      // 16896
#define BS_BYTES (BK * BS_ROW * 4)      // 16896
#define SSUM_OFF (AS_BYTES + BS_BYTES)  // 33792
#define SSUM_BYTES (NTHREADS * TMP * TN * 8)        // 65536
#define SMEM_TOTAL (SSUM_OFF + SSUM_BYTES)          // 99328 (x2 CTAs = 198.7KB)

typedef unsigned long long u64;

// Packed fp32x2 (Blackwell FFMA2). Each 32-bit lane gets IEEE fp32 .rn rounding
// identical to scalar fmaf/add — bit-exact per element, 2x scalar FLOP rate.
#define FMA_F32X2(d, a, b, c) \
    asm("fma.rn.f32x2 %0, %1, %2, %3;" : "=l"(d) : "l"(a), "l"(b), "l"(c))
#define ADD_F32X2_(d, a, b) \
    asm("add.rn.f32x2 %0, %1, %2;" : "=l"(d) : "l"(a), "l"(b))
#define PACK_F32X2_(out, lo, hi) \
    asm("mov.b64 %0, {%1, %2};" : "=l"(out) : "f"(lo), "f"(hi))
#define UNPACK_F32X2_(lo, hi, in) \
    asm("mov.b64 {%0, %1}, %2;" : "=f"(lo), "=f"(hi) : "l"(in))

// Scratch (no allocation allowed) — ping-pong activation buffers + u vectors.
__device__ float g_buf0[(size_t)DDIM * DDIM];
__device__ float g_buf1[(size_t)DDIM * DDIM];
__device__ float g_u1[DDIM];
__device__ float g_u2[DDIM];

// u[j] = (1/n) * (prod_{d,g} cos(uw[d, j, g]))^2   (closed form of _ultimate)
__global__ void ultimate_u_kernel(const float* __restrict__ uw1,
                                  const float* __restrict__ uw2,
                                  float* __restrict__ u1,
                                  float* __restrict__ u2) {
    int g = blockIdx.x * blockDim.x + threadIdx.x;
    const float* uw = (g < DDIM) ? uw1 : uw2;
    float* u        = (g < DDIM) ? u1  : u2;
    int j = (g < DDIM) ? g : g - DDIM;
    if (j >= DDIM) return;
    float p = 1.0f;
#pragma unroll
    for (int d = 0; d < DEPTH; d++) {
        size_t base = (size_t)d * DDIM * DDIM + (size_t)j * DDIM;
        p *= cosf(uw[base + 0]);
        p *= cosf(uw[base + 1]);
        p *= cosf(uw[base + 2]);
    }
    u[j] = p * p * (1.0f / (float)DDIM);
}

// MODE 0: C = relu(A @ W^T + bias)          W is [N,K] row-major
// MODE 1: C = tanh(A @ W + bias + u)        W is [K,N] row-major
// Thread map: 512 thr; warp = fixed ty (tid>>5), tx = tid&31.
//   thread owns rows ty*8..+7 (as 4 lane-pairs) x cols tx*4..+3.
//   a-loads: broadcast (one address/warp); b-loads: 512B contiguous/warp.
// Accumulation replicates the reference split-K=4: serial fp32 FMA (increasing
// k) within each contiguous 512-chunk; running sums (per-thread SMEM slots)
// folded in chunk order -> ((p0+p1)+p2)+p3 exactly.
template <int MODE>
__global__ __launch_bounds__(NTHREADS, 2) void gemm_kernel(
    const float* __restrict__ A, const float* __restrict__ W,
    const float* __restrict__ bias, const float* __restrict__ u,
    float* __restrict__ C)
{
    extern __shared__ char smem[];
    float* As = (float*)smem;                    // [BK][AS_ROW], transposed A
    float* Bs = (float*)(smem + AS_BYTES);       // [BK][BS_ROW], k-major B
    u64*   ssum = (u64*)(smem + SSUM_OFF);

    const int tid = threadIdx.x;
    const int tx = tid & 31;         // 0..31 -> N direction (TN=4 each)
    const int ty = tid >> 5;         // 0..15 -> M direction (8 rows each)
    const int m0 = blockIdx.y * BM;
    const int n0 = blockIdx.x * BN;

    // loader geometry (2 float4 per operand per tile)
    const int al_r0 = tid >> 3;                // + it*64, rows 0..127
    const int al_c4 = tid & 7;                 // k-group 0..7
    const int bl_r0 = tid >> 5;                // + it*16, k rows 0..31 (MODE1)
    const int bl_c  = tid & 31;                // n-group 0..31 (MODE1)

    u64 acc2[TMP][TN];               // lanes = adjacent row pair, per col
#pragma unroll
    for (int ip = 0; ip < TMP; ip++)
#pragma unroll
        for (int j = 0; j < TN; j++) acc2[ip][j] = 0ULL;

#pragma unroll 1
    for (int t = 0; t < NTILES; t++) {
        const int k0 = t * BK;
        // ---- A tile: rows m0..m0+127, cols k0..k0+31 -> As[k][m] (transposed)
#pragma unroll
        for (int it = 0; it < 2; it++) {
            int r = al_r0 + it * 64;
            float4 v = *(const float4*)(A + (size_t)(m0 + r) * DDIM + k0 + al_c4 * 4);
            As[(al_c4 * 4 + 0) * AS_ROW + r] = v.x;
            As[(al_c4 * 4 + 1) * AS_ROW + r] = v.y;
            As[(al_c4 * 4 + 2) * AS_ROW + r] = v.z;
            As[(al_c4 * 4 + 3) * AS_ROW + r] = v.w;
        }
        // ---- B tile -> Bs[k][n]
        if (MODE == 0) {
            // NT: W[n,k] -> transpose (same pattern as A)
#pragma unroll
            for (int it = 0; it < 2; it++) {
                int r = al_r0 + it * 64;
                float4 v = *(const float4*)(W + (size_t)(n0 + r) * DDIM + k0 + al_c4 * 4);
                Bs[(al_c4 * 4 + 0) * BS_ROW + r] = v.x;
                Bs[(al_c4 * 4 + 1) * BS_ROW + r] = v.y;
                Bs[(al_c4 * 4 + 2) * BS_ROW + r] = v.z;
                Bs[(al_c4 * 4 + 3) * BS_ROW + r] = v.w;
            }
        } else {
            // NN: W[k,n] -> direct copy
#pragma unroll
            for (int it = 0; it < 2; it++) {
                int r = bl_r0 + it * 16;
                float4 v = *(const float4*)(W + (size_t)(k0 + r) * DDIM + n0 + bl_c * 4);
                *(float4*)&Bs[r * BS_ROW + bl_c * 4] = v;
            }
        }
        __syncthreads();

#pragma unroll
        for (int k = 0; k < BK; k++) {
            // a: rows ty*8..+7 as 4 packed pairs — broadcast loads (1 addr/warp)
            u64 a2[TMP];
            *(ulonglong2*)&a2[0] = *(const ulonglong2*)&As[k * AS_ROW + ty * 8];
            *(ulonglong2*)&a2[2] = *(const ulonglong2*)&As[k * AS_ROW + ty * 8 + 4];
            // b: cols tx*4..+3 — 512B contiguous across warp, conflict-free
            float4 bv = *(const float4*)&Bs[k * BS_ROW + tx * 4];
            u64 b2[TN];
            PACK_F32X2_(b2[0], bv.x, bv.x);
            PACK_F32X2_(b2[1], bv.y, bv.y);
            PACK_F32X2_(b2[2], bv.z, bv.z);
            PACK_F32X2_(b2[3], bv.w, bv.w);
#pragma unroll
            for (int ip = 0; ip < TMP; ip++)
#pragma unroll
                for (int j = 0; j < TN; j++)
                    FMA_F32X2(acc2[ip][j], a2[ip], b2[j], acc2[ip][j]);
        }

        // chunk boundary: fold live partial into per-thread running sum in SMEM
        if ((t & (TILES_PER_CHUNK - 1)) == TILES_PER_CHUNK - 1) {
#pragma unroll
            for (int ip = 0; ip < TMP; ip++)
#pragma unroll
                for (int j = 0; j < TN; j++) {
                    int slot = (ip * TN + j) * NTHREADS + tid;
                    if (t == TILES_PER_CHUNK - 1) {
                        ssum[slot] = acc2[ip][j];
                    } else {
                        u64 s = ssum[slot];
                        ADD_F32X2_(s, s, acc2[ip][j]);
                        ssum[slot] = s;
                    }
                    acc2[ip][j] = 0ULL;
                }
        }
        __syncthreads();
    }

    // ---- fused epilogue
    const int colb = n0 + tx * 4;
    float bz[TN], uz[TN];
#pragma unroll
    for (int j = 0; j < TN; j++) {
        bz[j] = bias[colb + j];
        if (MODE == 1) uz[j] = u[colb + j];
    }
#pragma unroll
    for (int ip = 0; ip < TMP; ip++) {
        float lo[TN], hi[TN];
#pragma unroll
        for (int j = 0; j < TN; j++)
            UNPACK_F32X2_(lo[j], hi[j], ssum[(ip * TN + j) * NTHREADS + tid]);
#pragma unroll
        for (int e = 0; e < 2; e++) {
            int row = m0 + ty * 8 + ip * 2 + e;
            float* s = e ? hi : lo;
            float4 v;
            v.x = s[0] + bz[0];
            v.y = s[1] + bz[1];
            v.z = s[2] + bz[2];
            v.w = s[3] + bz[3];
            if (MODE == 1) {
                v.x = tanhf(v.x + uz[0]);
                v.y = tanhf(v.y + uz[1]);
                v.z = tanhf(v.z + uz[2]);
                v.w = tanhf(v.w + uz[3]);
            } else {
                v.x = fmaxf(v.x, 0.0f);
                v.y = fmaxf(v.y, 0.0f);
                v.z = fmaxf(v.z, 0.0f);
                v.w = fmaxf(v.w, 0.0f);
            }
            *(float4*)(C + (size_t)row * DDIM + colb) = v;
        }
    }
}

extern "C" void kernel_launch(void* const* d_in, const int* in_sizes, int n_in,
                              void* d_out, int out_size) {
    const float* x   = (const float*)d_in[0];
    const float* w0  = (const float*)d_in[1];
    const float* b0  = (const float*)d_in[2];
    const float* w1  = (const float*)d_in[3];
    const float* b1  = (const float*)d_in[4];
    const float* uw1 = (const float*)d_in[5];
    const float* cw1 = (const float*)d_in[6];
    const float* cb1 = (const float*)d_in[7];
    const float* w2  = (const float*)d_in[8];
    const float* b2  = (const float*)d_in[9];
    const float* uw2 = (const float*)d_in[10];
    const float* cw2 = (const float*)d_in[11];
    const float* cb2 = (const float*)d_in[12];
    const float* wf  = (const float*)d_in[13];
    const float* bf  = (const float*)d_in[14];
    float* out = (float*)d_out;

    float *buf0, *buf1, *u1, *u2;
    cudaGetSymbolAddress((void**)&buf0, g_buf0);
    cudaGetSymbolAddress((void**)&buf1, g_buf1);
    cudaGetSymbolAddress((void**)&u1, g_u1);
    cudaGetSymbolAddress((void**)&u2, g_u2);

    // opt-in to >48KB dynamic smem (host-side attribute, not a stream op)
    cudaFuncSetAttribute(gemm_kernel<0>, cudaFuncAttributeMaxDynamicSharedMemorySize, SMEM_TOTAL);
    cudaFuncSetAttribute(gemm_kernel<1>, cudaFuncAttributeMaxDynamicSharedMemorySize, SMEM_TOTAL);

    dim3 grid(DDIM / BN, DDIM / BM);
    dim3 block(NTHREADS);

    // closed-form "quantum" vectors (both in one launch)
    ultimate_u_kernel<<<2 * DDIM / 256, 256>>>(uw1, uw2, u1, u2);

    // 1) h = relu(x @ w0^T + b0)
    gemm_kernel<0><<<grid, block, SMEM_TOTAL>>>(x, w0, b0, nullptr, buf0);
    // 2) h = relu(h @ w1^T + b1)
    gemm_kernel<0><<<grid, block, SMEM_TOTAL>>>(buf0, w1, b1, nullptr, buf1);
    // 3) h = tanh(h @ cw1 + cb1 + u1)
    gemm_kernel<1><<<grid, block, SMEM_TOTAL>>>(buf1, cw1, cb1, u1, buf0);
    // 4) h = relu(h @ w2^T + b2)
    gemm_kernel<0><<<grid, block, SMEM_TOTAL>>>(buf0, w2, b2, nullptr, buf1);
    // 5) h = tanh(h @ cw2 + cb2 + u2)
    gemm_kernel<1><<<grid, block, SMEM_TOTAL>>>(buf1, cw2, cb2, u2, buf0);
    // 6) out = relu(h @ wf^T + bf)
    gemm_kernel<0><<<grid, block, SMEM_TOTAL>>>(buf0, wf, bf, nullptr, out);
}

// round 16
// speedup vs baseline: 1.0734x; 1.0734x over previous
#include <cuda_runtime.h>
#include <math.h>

#define DDIM 2048
#define DEPTH 9
#define BM 128
#define BN 128
#define BK 16
#define TM 8
#define TN 8
#define NTHREADS 256
#define NCHUNK 4
#define TILES_PER_CHUNK ((DDIM / NCHUNK) / BK)   // 32
#define NTILES (DDIM / BK)                        // 128

#define AS_ROW (BM + 4)                 // 132 floats
#define BS_ROW (BN + 4)                 // 132 floats
#define AS_BYTES (BK * AS_ROW * 4)      // 8448
#define BS_BYTES (BK * BS_ROW * 4)      // 8448
#define BUF_BYTES (AS_BYTES + BS_BYTES) // 16896
#define SSUM_OFF (2 * BUF_BYTES)        // 33792
#define SSUM_BYTES (NTHREADS * TM * (TN / 2) * 8)   // 65536
#define SMEM_TOTAL (SSUM_OFF + SSUM_BYTES)          // 99328 (x2 CTAs = 194KB < 228KB)

typedef unsigned long long u64;

// Packed fp32x2 (Blackwell FFMA2). Each 32-bit lane gets IEEE fp32 .rn rounding
// identical to scalar fmaf/add — bit-exact per element, 2x scalar FLOP rate.
#define FMA_F32X2(d, a, b, c) \
    asm("fma.rn.f32x2 %0, %1, %2, %3;" : "=l"(d) : "l"(a), "l"(b), "l"(c))
#define ADD_F32X2_(d, a, b) \
    asm("add.rn.f32x2 %0, %1, %2;" : "=l"(d) : "l"(a), "l"(b))
#define PACK_F32X2_(out, lo, hi) \
    asm("mov.b64 %0, {%1, %2};" : "=l"(out) : "f"(lo), "f"(hi))
#define UNPACK_F32X2_(lo, hi, in) \
    asm("mov.b64 {%0, %1}, %2;" : "=f"(lo), "=f"(hi) : "l"(in))

// Conflict-free B column remap (16-wide tx, TN=8):
//   col c: f(c) = ((c>>2)&1)*64 + (c>>3)*4 + (c&3)
// Thread tx's two ulonglong2 reads sit at floats {tx*4} and {64+tx*4}:
// 16 lanes x 16B contiguous per read -> conflict-free.

// Scratch (no allocation allowed) — ping-pong activation buffers + u vectors.
__device__ float g_buf0[(size_t)DDIM * DDIM];
__device__ float g_buf1[(size_t)DDIM * DDIM];
__device__ float g_u1[DDIM];
__device__ float g_u2[DDIM];

// u[j] = (1/n) * (prod_{d,g} cos(uw[d, j, g]))^2   (closed form of _ultimate)
__global__ void ultimate_u_kernel(const float* __restrict__ uw1,
                                  const float* __restrict__ uw2,
                                  float* __restrict__ u1,
                                  float* __restrict__ u2) {
    int g = blockIdx.x * blockDim.x + threadIdx.x;
    const float* uw = (g < DDIM) ? uw1 : uw2;
    float* u        = (g < DDIM) ? u1  : u2;
    int j = (g < DDIM) ? g : g - DDIM;
    if (j >= DDIM) return;
    float p = 1.0f;
#pragma unroll
    for (int d = 0; d < DEPTH; d++) {
        size_t base = (size_t)d * DDIM * DDIM + (size_t)j * DDIM;
        p *= cosf(uw[base + 0]);
        p *= cosf(uw[base + 1]);
        p *= cosf(uw[base + 2]);
    }
    u[j] = p * p * (1.0f / (float)DDIM);
}

// MODE 0: C = relu(A @ W^T + bias)          W is [N,K] row-major
// MODE 1: C = tanh(A @ W + bias + u)        W is [K,N] row-major
// Accumulation replicates the reference split-K=4: serial fp32 FMA (increasing
// k) within each contiguous 512-chunk; running sums (per-thread SMEM slots)
// folded in chunk order -> ((p0+p1)+p2)+p3 exactly.
// Double-buffered SMEM pipeline: LDG t+1 || compute t || STS t+1, 1 barrier/tile.
template <int MODE>
__global__ __launch_bounds__(NTHREADS, 2) void gemm_kernel(
    const float* __restrict__ A, const float* __restrict__ W,
    const float* __restrict__ bias, const float* __restrict__ u,
    float* __restrict__ C)
{
    extern __shared__ char smem[];
    u64* ssum = (u64*)(smem + SSUM_OFF);

    const int tid = threadIdx.x;
    const int tx = tid & 15;         // 0..15 -> N direction (TN=8 each)
    const int ty = tid >> 4;         // 0..15 -> M direction (TM=8 each)
    const int m0 = blockIdx.y * BM;
    const int n0 = blockIdx.x * BN;

    // loader geometry (2 float4 per operand per tile)
    const int al_r0 = tid >> 2;                // + it*64, rows 0..127
    const int al_c4 = tid & 3;                 // k-group 0..3
    const int f0 = ((al_r0 >> 2) & 1) * 64 + (al_r0 >> 3) * 4 + (al_r0 & 3); // f(al_r0)
    const int bl_r0 = tid >> 5;                // + it*8, k rows 0..15 (MODE1)
    const int bl_c  = tid & 31;                // n-group 0..31 (MODE1)
    const int bl_f  = (bl_c & 1) * 64 + (bl_c >> 1) * 4;  // f(4*bl_c)

    u64 acc2[TM][TN / 2];            // live chunk accumulator, packed col pairs
#pragma unroll
    for (int i = 0; i < TM; i++)
#pragma unroll
        for (int jp = 0; jp < TN / 2; jp++) acc2[i][jp] = 0ULL;

    float4 ra[2], rb[2];

    // ---- prologue: LDG tile 0 and stage into buffer 0
    {
#pragma unroll
        for (int it = 0; it < 2; it++) {
            int r = al_r0 + it * 64;
            ra[it] = *(const float4*)(A + (size_t)(m0 + r) * DDIM + al_c4 * 4);
        }
        if (MODE == 0) {
#pragma unroll
            for (int it = 0; it < 2; it++) {
                int r = al_r0 + it * 64;
                rb[it] = *(const float4*)(W + (size_t)(n0 + r) * DDIM + al_c4 * 4);
            }
        } else {
#pragma unroll
            for (int it = 0; it < 2; it++) {
                int r = bl_r0 + it * 8;
                rb[it] = *(const float4*)(W + (size_t)r * DDIM + n0 + bl_c * 4);
            }
        }
        float* As = (float*)(smem);
        float* Bs = (float*)(smem + AS_BYTES);
#pragma unroll
        for (int it = 0; it < 2; it++) {
            int r = al_r0 + it * 64;
            As[(al_c4 * 4 + 0) * AS_ROW + r] = ra[it].x;
            As[(al_c4 * 4 + 1) * AS_ROW + r] = ra[it].y;
            As[(al_c4 * 4 + 2) * AS_ROW + r] = ra[it].z;
            As[(al_c4 * 4 + 3) * AS_ROW + r] = ra[it].w;
        }
        if (MODE == 0) {
#pragma unroll
            for (int it = 0; it < 2; it++) {
                int f = f0 + it * 32;
                Bs[(al_c4 * 4 + 0) * BS_ROW + f] = rb[it].x;
                Bs[(al_c4 * 4 + 1) * BS_ROW + f] = rb[it].y;
                Bs[(al_c4 * 4 + 2) * BS_ROW + f] = rb[it].z;
                Bs[(al_c4 * 4 + 3) * BS_ROW + f] = rb[it].w;
            }
        } else {
#pragma unroll
            for (int it = 0; it < 2; it++) {
                int r = bl_r0 + it * 8;
                *(float4*)&Bs[r * BS_ROW + bl_f] = rb[it];
            }
        }
    }
    __syncthreads();

    // ---- main pipeline
#pragma unroll 1
    for (int t = 0; t < NTILES; t++) {
        const int cur = t & 1;

        // prefetch tile t+1 (GMEM -> regs), independent of SMEM
        if (t + 1 < NTILES) {
            const int k0 = (t + 1) * BK;
#pragma unroll
            for (int it = 0; it < 2; it++) {
                int r = al_r0 + it * 64;
                ra[it] = *(const float4*)(A + (size_t)(m0 + r) * DDIM + k0 + al_c4 * 4);
            }
            if (MODE == 0) {
#pragma unroll
                for (int it = 0; it < 2; it++) {
                    int r = al_r0 + it * 64;
                    rb[it] = *(const float4*)(W + (size_t)(n0 + r) * DDIM + k0 + al_c4 * 4);
                }
            } else {
#pragma unroll
                for (int it = 0; it < 2; it++) {
                    int r = bl_r0 + it * 8;
                    rb[it] = *(const float4*)(W + (size_t)(k0 + r) * DDIM + n0 + bl_c * 4);
                }
            }
        }

        // compute on current buffer
        {
            const float* As = (const float*)(smem + cur * BUF_BYTES);
            const float* Bs = (const float*)(smem + cur * BUF_BYTES + AS_BYTES);
#pragma unroll
            for (int k = 0; k < BK; k++) {
                float a[TM];
                u64 a2[TM], b2[TN / 2];
                *(float4*)&a[0] = *(const float4*)&As[k * AS_ROW + ty * TM];
                *(float4*)&a[4] = *(const float4*)&As[k * AS_ROW + ty * TM + 4];
#pragma unroll
                for (int i = 0; i < TM; i++)
                    PACK_F32X2_(a2[i], a[i], a[i]);
                *(ulonglong2*)&b2[0] = *(const ulonglong2*)&Bs[k * BS_ROW + tx * 4];
                *(ulonglong2*)&b2[2] = *(const ulonglong2*)&Bs[k * BS_ROW + 64 + tx * 4];
#pragma unroll
                for (int i = 0; i < TM; i++)
#pragma unroll
                    for (int jp = 0; jp < TN / 2; jp++)
                        FMA_F32X2(acc2[i][jp], a2[i], b2[jp], acc2[i][jp]);
            }
        }

        // stage tile t+1 into the other buffer (safe: distinct buffer)
        if (t + 1 < NTILES) {
            float* As = (float*)(smem + (cur ^ 1) * BUF_BYTES);
            float* Bs = (float*)(smem + (cur ^ 1) * BUF_BYTES + AS_BYTES);
#pragma unroll
            for (int it = 0; it < 2; it++) {
                int r = al_r0 + it * 64;
                As[(al_c4 * 4 + 0) * AS_ROW + r] = ra[it].x;
                As[(al_c4 * 4 + 1) * AS_ROW + r] = ra[it].y;
                As[(al_c4 * 4 + 2) * AS_ROW + r] = ra[it].z;
                As[(al_c4 * 4 + 3) * AS_ROW + r] = ra[it].w;
            }
            if (MODE == 0) {
#pragma unroll
                for (int it = 0; it < 2; it++) {
                    int f = f0 + it * 32;
                    Bs[(al_c4 * 4 + 0) * BS_ROW + f] = rb[it].x;
                    Bs[(al_c4 * 4 + 1) * BS_ROW + f] = rb[it].y;
                    Bs[(al_c4 * 4 + 2) * BS_ROW + f] = rb[it].z;
                    Bs[(al_c4 * 4 + 3) * BS_ROW + f] = rb[it].w;
                }
            } else {
#pragma unroll
                for (int it = 0; it < 2; it++) {
                    int r = bl_r0 + it * 8;
                    *(float4*)&Bs[r * BS_ROW + bl_f] = rb[it];
                }
            }
        }

        // chunk boundary: fold live partial into per-thread running sum in SMEM
        if ((t & (TILES_PER_CHUNK - 1)) == TILES_PER_CHUNK - 1) {
#pragma unroll
            for (int i = 0; i < TM; i++)
#pragma unroll
                for (int jp = 0; jp < TN / 2; jp++) {
                    int slot = (i * (TN / 2) + jp) * NTHREADS + tid;
                    if (t == TILES_PER_CHUNK - 1) {
                        ssum[slot] = acc2[i][jp];
                    } else {
                        u64 s = ssum[slot];
                        ADD_F32X2_(s, s, acc2[i][jp]);
                        ssum[slot] = s;
                    }
                    acc2[i][jp] = 0ULL;
                }
        }

        __syncthreads();
    }

    // ---- fused epilogue (read combined sums from SMEM)
#pragma unroll
    for (int i = 0; i < TM; i++) {
        int row = m0 + ty * TM + i;
#pragma unroll
        for (int j = 0; j < TN; j += 4) {
            int col = n0 + tx * TN + j;
            int s0i = (i * (TN / 2) + j / 2) * NTHREADS + tid;
            int s1i = (i * (TN / 2) + j / 2 + 1) * NTHREADS + tid;
            float s0, s1, s2, s3;
            UNPACK_F32X2_(s0, s1, ssum[s0i]);
            UNPACK_F32X2_(s2, s3, ssum[s1i]);
            float4 v;
            v.x = s0 + bias[col + 0];
            v.y = s1 + bias[col + 1];
            v.z = s2 + bias[col + 2];
            v.w = s3 + bias[col + 3];
            if (MODE == 1) {
                v.x = tanhf(v.x + u[col + 0]);
                v.y = tanhf(v.y + u[col + 1]);
                v.z = tanhf(v.z + u[col + 2]);
                v.w = tanhf(v.w + u[col + 3]);
            } else {
                v.x = fmaxf(v.x, 0.0f);
                v.y = fmaxf(v.y, 0.0f);
                v.z = fmaxf(v.z, 0.0f);
                v.w = fmaxf(v.w, 0.0f);
            }
            *(float4*)(C + (size_t)row * DDIM + col) = v;
        }
    }
}

extern "C" void kernel_launch(void* const* d_in, const int* in_sizes, int n_in,
                              void* d_out, int out_size) {
    const float* x   = (const float*)d_in[0];
    const float* w0  = (const float*)d_in[1];
    const float* b0  = (const float*)d_in[2];
    const float* w1  = (const float*)d_in[3];
    const float* b1  = (const float*)d_in[4];
    const float* uw1 = (const float*)d_in[5];
    const float* cw1 = (const float*)d_in[6];
    const float* cb1 = (const float*)d_in[7];
    const float* w2  = (const float*)d_in[8];
    const float* b2  = (const float*)d_in[9];
    const float* uw2 = (const float*)d_in[10];
    const float* cw2 = (const float*)d_in[11];
    const float* cb2 = (const float*)d_in[12];
    const float* wf  = (const float*)d_in[13];
    const float* bf  = (const float*)d_in[14];
    float* out = (float*)d_out;

    float *buf0, *buf1, *u1, *u2;
    cudaGetSymbolAddress((void**)&buf0, g_buf0);
    cudaGetSymbolAddress((void**)&buf1, g_buf1);
    cudaGetSymbolAddress((void**)&u1, g_u1);
    cudaGetSymbolAddress((void**)&u2, g_u2);

    // opt-in to >48KB dynamic smem (host-side attribute, not a stream op)
    cudaFuncSetAttribute(gemm_kernel<0>, cudaFuncAttributeMaxDynamicSharedMemorySize, SMEM_TOTAL);
    cudaFuncSetAttribute(gemm_kernel<1>, cudaFuncAttributeMaxDynamicSharedMemorySize, SMEM_TOTAL);

    dim3 grid(DDIM / BN, DDIM / BM);
    dim3 block(NTHREADS);

    // closed-form "quantum" vectors (both in one launch)
    ultimate_u_kernel<<<2 * DDIM / 256, 256>>>(uw1, uw2, u1, u2);

    // 1) h = relu(x @ w0^T + b0)
    gemm_kernel<0><<<grid, block, SMEM_TOTAL>>>(x, w0, b0, nullptr, buf0);
    // 2) h = relu(h @ w1^T + b1)
    gemm_kernel<0><<<grid, block, SMEM_TOTAL>>>(buf0, w1, b1, nullptr, buf1);
    // 3) h = tanh(h @ cw1 + cb1 + u1)
    gemm_kernel<1><<<grid, block, SMEM_TOTAL>>>(buf1, cw1, cb1, u1, buf0);
    // 4) h = relu(h @ w2^T + b2)
    gemm_kernel<0><<<grid, block, SMEM_TOTAL>>>(buf0, w2, b2, nullptr, buf1);
    // 5) h = tanh(h @ cw2 + cb2 + u2)
    gemm_kernel<1><<<grid, block, SMEM_TOTAL>>>(buf1, cw2, cb2, u2, buf0);
    // 6) out = relu(h @ wf^T + bf)
    gemm_kernel<0><<<grid, block, SMEM_TOTAL>>>(buf0, wf, bf, nullptr, out);
}